// round 13
// baseline (speedup 1.0000x reference)
#include <cuda_runtime.h>
#include <math.h>

#define BATCH 2
#define NTOK 256
#define NATOM 2048
#define TSZ 64                   // atoms per tile
#define NTILE 32                 // NATOM / TSZ
#define TPAIRS 528               // NTILE*(NTILE+1)/2
#define GRIDB (TPAIRS * BATCH)   // 1056 pair blocks
#define NTB 128
#define NBUK 16
#define STILE 64                 // 8x8 grid of 32x32 S tiles per batch
#define ABLK 8                   // atom/moment blocks per batch

// ---------------- device scratch (no allocations allowed) ----------------
__device__ double     g_acc[BATCH][4][NBUK];   // bond_num, bond_den, ce, c (tail resets)
__device__ double     g_mom[BATCH][17];        // tail resets
__device__ ulonglong2 g_posA[BATCH][NATOM];    // (pack(x0,g0), pack(x1,g1))
__device__ ulonglong2 g_posB[BATCH][NATOM];    // (pack(x2,g2), pack(mask,nuc))
__device__ ulonglong2 g_negA[BATCH][NATOM];    // negated coords
__device__ ulonglong2 g_negB[BATCH][NATOM];    // (pack(-x2,-g2), pack(mask,nuc))
__device__ int        g_tok[BATCH][NATOM];
__device__ float      g_watom[BATCH][NATOM];
__device__ float      g_S[BATCH][NTOK * NTOK];
__device__ unsigned   g_done = 0;              // tail resets

__device__ __forceinline__ float sqrt_approx(float v) {
    float y; asm("sqrt.approx.f32 %0, %1;" : "=f"(y) : "f"(v)); return y;
}
__device__ __forceinline__ unsigned long long pack2(float lo, float hi) {
    unsigned long long r; asm("mov.b64 %0, {%1, %2};" : "=l"(r) : "f"(lo), "f"(hi)); return r;
}
__device__ __forceinline__ void unpack2(unsigned long long v, float& lo, float& hi) {
    asm("mov.b64 {%0, %1}, %2;" : "=f"(lo), "=f"(hi) : "l"(v));
}
__device__ __forceinline__ unsigned long long add2(unsigned long long a, unsigned long long b) {
    unsigned long long r; asm("add.rn.f32x2 %0, %1, %2;" : "=l"(r) : "l"(a), "l"(b)); return r;
}
__device__ __forceinline__ unsigned long long fma2(unsigned long long a, unsigned long long b,
                                                   unsigned long long c) {
    unsigned long long r; asm("fma.rn.f32x2 %0, %1, %2, %3;" : "=l"(r) : "l"(a), "l"(b), "l"(c)); return r;
}
__device__ __forceinline__ float det3f(float a00, float a01, float a02,
                                       float a10, float a11, float a12,
                                       float a20, float a21, float a22) {
    return a00*(a11*a22 - a12*a21) - a01*(a10*a22 - a12*a20) + a02*(a10*a21 - a11*a20);
}

// ================= Kernel A: prep (unchanged R12) ==========================
__global__ void __launch_bounds__(256)
prep_kernel(const float* __restrict__ x, const float* __restrict__ gt,
            const float* __restrict__ gmask,
            const float* __restrict__ isp, const float* __restrict__ isd,
            const float* __restrict__ isr, const float* __restrict__ isl,
            const float* __restrict__ tmask, const int* __restrict__ npt,
            const float* __restrict__ tb) {
    int b   = blockIdx.y;
    int tid = threadIdx.x;
    int lane = tid & 31, warp = tid >> 5;
    const float* tbb = tb + (size_t)b * NTOK * NTOK;

    if (blockIdx.x < STILE) {
        int tI = (blockIdx.x >> 3) << 5;
        int tJ = (blockIdx.x & 7) << 5;

        __shared__ float tA[32][33];
        __shared__ float tB[32][33];
        __shared__ float aI[32], pI[32], aJ[32], pJ[32];

        int r0 = tid >> 5;
        int c  = tid & 31;
        #pragma unroll
        for (int pss = 0; pss < 4; pss++) {
            int r = pss * 8 + r0;
            tA[r][c] = tbb[(tI + r) * NTOK + tJ + c];
            tB[r][c] = tbb[(tJ + r) * NTOK + tI + c];
        }
        if (tid < 32) {
            float tm = tmask[b * NTOK + tI + tid];
            aI[tid] = isl[b * NTOK + tI + tid] * tm;
            pI[tid] = (isp[b*NTOK+tI+tid] + isd[b*NTOK+tI+tid] + isr[b*NTOK+tI+tid]) * tm;
        } else if (tid < 64) {
            int q = tid - 32;
            float tm = tmask[b * NTOK + tJ + q];
            aJ[q] = isl[b * NTOK + tJ + q] * tm;
            pJ[q] = (isp[b*NTOK+tJ+q] + isd[b*NTOK+tJ+q] + isr[b*NTOK+tJ+q]) * tm;
        }
        __syncthreads();

        #pragma unroll
        for (int pss = 0; pss < 4; pss++) {
            int ri = pss * 8 + r0;
            g_S[b][(tI + ri) * NTOK + tJ + c] =
                tA[ri][c] * aI[ri] * pJ[c] + tB[c][ri] * aJ[c] * pI[ri];
        }
        return;
    }

    __shared__ int   cum[NTOK];
    __shared__ float s_nuc[NTOK], s_w[NTOK], s_ab[NTOK];

    {
        float tm = tmask[b * NTOK + tid];
        float dv = isd[b * NTOK + tid];
        float rv = isr[b * NTOK + tid];
        float lv = isl[b * NTOK + tid];
        float pv = isp[b * NTOK + tid];
        s_nuc[tid] = (dv + rv) * tm;
        s_w[tid]   = (1.0f + 5.0f * dv + 5.0f * rv + 10.0f * lv) * tm;
        s_ab[tid]  = (lv * tm) * ((pv + dv + rv) * tm);
        cum[tid]   = npt[b * NTOK + tid];
    }
    __syncthreads();
    for (int off = 1; off < NTOK; off <<= 1) {
        int v = (tid >= off) ? cum[tid - off] : 0;
        __syncthreads();
        cum[tid] += v;
        __syncthreads();
    }
    int total = cum[NTOK - 1];

    const float* xb = x  + (size_t)b * NATOM * 3;
    const float* gb = gt + (size_t)b * NATOM * 3;
    const float* mb = gmask + (size_t)b * NATOM;

    int l = (int)(blockIdx.x - STILE) * 256 + tid;
    int ls = l < total ? l : (total > 0 ? total - 1 : 0);
    int lo = 0, hi = NTOK - 1;
    while (lo < hi) {
        int mid = (lo + hi) >> 1;
        if (cum[mid] > ls) hi = mid; else lo = mid + 1;
    }
    int tok = lo;
    float valid = (l < total) ? 1.f : 0.f;
    float nuc  = s_nuc[tok] * valid;
    float w_at = s_w[tok] * valid;
    float ab   = s_ab[tok] * valid;

    float mk = mb[l];
    float x0 = xb[3*l+0], x1 = xb[3*l+1], x2 = xb[3*l+2];
    float g0 = gb[3*l+0], g1 = gb[3*l+1], g2 = gb[3*l+2];

    g_posA[b][l] = make_ulonglong2(pack2(x0, g0), pack2(x1, g1));
    g_posB[b][l] = make_ulonglong2(pack2(x2, g2), pack2(mk, nuc));
    g_negA[b][l] = make_ulonglong2(pack2(-x0, -g0), pack2(-x1, -g1));
    g_negB[b][l] = make_ulonglong2(pack2(-x2, -g2), pack2(mk, nuc));
    g_tok[b][l]   = tok;
    g_watom[b][l] = w_at;

    float s[18];
    float wm = w_at * mk;
    s[0] = wm; s[1] = mk;
    s[2] = wm*x0; s[3] = wm*x1; s[4] = wm*x2;
    s[5] = wm*g0; s[6] = wm*g1; s[7] = wm*g2;
    s[8]  = wm*x0*g0; s[9]  = wm*x0*g1; s[10] = wm*x0*g2;
    s[11] = wm*x1*g0; s[12] = wm*x1*g1; s[13] = wm*x1*g2;
    s[14] = wm*x2*g0; s[15] = wm*x2*g1; s[16] = wm*x2*g2;
    s[17] = ab * __ldg(&tbb[tok * NTOK + tok]) * mk * mk;

    __shared__ double redm[8][18];
    #pragma unroll
    for (int q = 0; q < 18; q++) {
        double v = (double)s[q];
        for (int off = 16; off > 0; off >>= 1) v += __shfl_xor_sync(0xffffffffu, v, off);
        if (lane == 0) redm[warp][q] = v;
    }
    __syncthreads();
    if (tid < 17) {
        double v = 0.0;
        #pragma unroll
        for (int ww = 0; ww < 8; ww++) v += redm[ww][tid];
        atomicAdd(&g_mom[b][tid], v);
    }
    if (tid == 17) {
        double v = 0.0;
        #pragma unroll
        for (int ww = 0; ww < 8; ww++) v += redm[ww][17];
        atomicAdd(&g_acc[b][1][0], v);
    }
}

// ================= Kernel B: pairwise + tail ==============================
// TRANSPOSED mapping: thread owns COLUMN atom (tile J, registers, positive);
// iterates over ROW atoms (tile I, smem, negated). Bond LDG is warp-uniform
// in the row token -> one 32B sector per warp per iteration.
template<bool DIAG>
__device__ __forceinline__ void pair_loop(
    int tid,
    const ulonglong2 cA, const ulonglong2 cB, float cmask, float cnuc,
    int c, const float* Scol,
    const ulonglong2* srA, const ulonglong2* srB, const int* srT,
    float& a0, float& a1, float& a2, float& a3)
{
    int ib = (tid & 1) << 5;
    const unsigned long long EPS2 = pack2(1e-12f, 1e-12f);

    const float n1 = 0.846045767f,  n2 = 0.187663961f,  n3 = 0.0091748690f;
    const float q1 = 1.128061023f,  q2 = 0.375327923f,  q3 = 0.036699476f, q4 = 0.00055308437f;

    #pragma unroll 4
    for (int jj = 0; jj < 32; jj++) {
        int i = ib + jj;
        ulonglong2 rA = srA[i];           // negated row coords
        ulonglong2 rB = srB[i];

        unsigned long long d0 = add2(cA.x, rA.x);
        unsigned long long d1 = add2(cA.y, rA.y);
        unsigned long long d2 = add2(cB.x, rB.x);
        unsigned long long tt = fma2(d0, d0, EPS2);
        tt = fma2(d1, d1, tt);
        tt = fma2(d2, d2, tt);
        float ssx, ssg;
        unpack2(tt, ssx, ssg);
        float dxv = sqrt_approx(ssx);
        float dgv = sqrt_approx(ssg);

        float rmask, rnuc;
        unpack2(rB.y, rmask, rnuc);
        float pm = cmask * rmask;
        if (DIAG) pm = (c > i) ? pm : 0.f;

        float diff = dxv - dgv;
        float wS = __ldg(&Scol[srT[i] * NTOK]);   // warp-uniform row, lane cols in 1 sector
        float wbs = wS * pm;
        a0 = fmaf(diff * diff, wbs, a0);
        a1 += wbs;

        float d = fminf(fabsf(diff), 20.f);
        float E = __expf(d);
        float num = fmaf(fmaf(fmaf(n3, E, n2), E, n1), E, 1.f);
        float den = fmaf(fmaf(fmaf(fmaf(q4, E, q3), E, q2), E, q1), E, 1.f);
        float e   = __fdividef(num, den);

        float nus = cnuc + rnuc;
        float cc = (dgv < 15.f) ? 2.f : ((dgv < 30.f) ? nus : 0.f);
        float csum = cc * pm;

        a2 = fmaf(csum, e, a2);
        a3 += csum;
    }
}

__global__ void __launch_bounds__(NTB, 8)
pair_kernel(const float* __restrict__ x, const float* __restrict__ gt,
            const float* __restrict__ gmask, const float* __restrict__ t,
            float* __restrict__ out) {
    int blk = blockIdx.x;
    int tid = threadIdx.x;
    int b = blk & 1;
    int p = blk >> 1;
    int I = 0, rem = p;
    while (rem >= (NTILE - I)) { rem -= (NTILE - I); I++; }
    int J = I + rem;

    __shared__ ulonglong2 srA[TSZ], srB[TSZ];
    __shared__ int        srT[TSZ];

    // row tile I (negated) into smem
    if (tid < TSZ) {
        srA[tid]  = g_negA[b][I * TSZ + tid];
        srT[tid]  = g_tok[b][I * TSZ + tid];
    } else {
        int li = tid - TSZ;
        srB[li] = g_negB[b][I * TSZ + li];
    }

    // column atom per thread (positive copy), from global
    int c = tid >> 1;
    int lc = J * TSZ + c;
    ulonglong2 cA = g_posA[b][lc];
    ulonglong2 cB = g_posB[b][lc];
    float cmask, cnuc;
    unpack2(cB.y, cmask, cnuc);
    const float* Scol = &g_S[b][g_tok[b][lc]];
    __syncthreads();

    float a0 = 0.f, a1 = 0.f, a2 = 0.f, a3 = 0.f;
    if (I == J) pair_loop<true >(tid, cA, cB, cmask, cnuc, c, Scol, srA, srB, srT, a0, a1, a2, a3);
    else        pair_loop<false>(tid, cA, cB, cmask, cnuc, c, Scol, srA, srB, srT, a0, a1, a2, a3);

    int lane = tid & 31, warp = tid >> 5;
    {
        __shared__ float red2[4][4];
        float vals[4] = {a0, a1, a2, a3};
        #pragma unroll
        for (int k = 0; k < 4; k++) {
            float v = vals[k];
            for (int off = 16; off > 0; off >>= 1) v += __shfl_xor_sync(0xffffffffu, v, off);
            if (lane == 0) red2[warp][k] = v;
        }
        __syncthreads();
        if (tid < 4) {
            float ssum = red2[0][tid] + red2[1][tid] + red2[2][tid] + red2[3][tid];
            atomicAdd(&g_acc[b][tid][(blk >> 1) & (NBUK - 1)], (double)ssum);
        }
    }

    // ---- done counter: last finishing block runs the tail -----------------
    __shared__ int s_last;
    __threadfence();
    __syncthreads();
    if (tid == 0) {
        unsigned v = atomicAdd(&g_done, 1u);
        s_last = (v == GRIDB - 1) ? 1 : 0;
    }
    __syncthreads();
    if (!s_last) return;
    __threadfence();   // acquire

    // =========== tail: QCP Kabsch + weighted MSE + final ====================
    __shared__ float sR[BATCH][15];
    __shared__ double sred[4];

    if (tid < BATCH) {
        int bb = tid;
        double W = g_mom[bb][0];
        double invW = 1.0 / W;
        double sx[3] = {g_mom[bb][2], g_mom[bb][3], g_mom[bb][4]};
        double sg[3] = {g_mom[bb][5], g_mom[bb][6], g_mom[bb][7]};
        double H[3][3];
        for (int i = 0; i < 3; i++)
            for (int j = 0; j < 3; j++)
                H[i][j] = g_mom[bb][8 + i * 3 + j] - sx[i] * sg[j] * invW;

        double Sxx = H[0][0], Sxy = H[1][0], Sxz = H[2][0];
        double Syx = H[0][1], Syy = H[1][1], Syz = H[2][1];
        double Szx = H[0][2], Szy = H[1][2], Szz = H[2][2];

        double Nd[4][4] = {
            { Sxx+Syy+Szz,  Syz-Szy,       Szx-Sxz,       Sxy-Syx      },
            { Syz-Szy,      Sxx-Syy-Szz,   Sxy+Syx,       Szx+Sxz      },
            { Szx-Sxz,      Sxy+Syx,      -Sxx+Syy-Szz,   Syz+Szy      },
            { Sxy-Syx,      Szx+Sxz,       Syz+Szy,      -Sxx-Syy+Szz  }};

        double fro = 0.0;
        for (int i = 0; i < 4; i++) for (int j = 0; j < 4; j++) fro += Nd[i][j]*Nd[i][j];
        double scl = 1.0 / sqrt(fro + 1e-300);

        float N[4][4];
        for (int i = 0; i < 4; i++)
            for (int j = 0; j < 4; j++) N[i][j] = (float)(Nd[i][j] * scl);

        float N2[4][4]; float t3 = 0.f, t4 = 0.f;
        #pragma unroll
        for (int i = 0; i < 4; i++)
            #pragma unroll
            for (int j = 0; j < 4; j++) {
                float v = 0.f;
                #pragma unroll
                for (int k = 0; k < 4; k++) v = fmaf(N[i][k], N[k][j], v);
                N2[i][j] = v;
            }
        #pragma unroll
        for (int i = 0; i < 4; i++)
            #pragma unroll
            for (int j = 0; j < 4; j++) {
                t3 = fmaf(N2[i][j], N[i][j], t3);
                t4 = fmaf(N2[i][j], N2[i][j], t4);
            }
        const float a2c = -0.5f;
        float a1c = -t3 * (1.f / 3.f);
        float a0c = 0.125f - 0.25f * t4;

        float lam = 1.0f;
        #pragma unroll
        for (int it = 0; it < 16; it++) {
            float pp = fmaf(fmaf(fmaf(lam, lam, a2c), lam, a1c), lam, a0c);
            float dp = fmaf(fmaf(4.f, lam * lam, 2.f * a2c), lam, a1c);
            lam -= __fdividef(pp, dp);
        }

        float M[4][4];
        for (int i = 0; i < 4; i++)
            for (int j = 0; j < 4; j++) M[i][j] = N[i][j] - ((i == j) ? lam : 0.f);

        float adj[4][4];
        const int rows[4][3] = {{1,2,3},{0,2,3},{0,1,3},{0,1,2}};
        #pragma unroll
        for (int i = 0; i < 4; i++)
            #pragma unroll
            for (int j = 0; j < 4; j++) {
                const int* rr = rows[j];
                const int* cc = rows[i];
                float m3 = det3f(M[rr[0]][cc[0]], M[rr[0]][cc[1]], M[rr[0]][cc[2]],
                                 M[rr[1]][cc[0]], M[rr[1]][cc[1]], M[rr[1]][cc[2]],
                                 M[rr[2]][cc[0]], M[rr[2]][cc[1]], M[rr[2]][cc[2]]);
                adj[i][j] = (((i + j) & 1) ? -m3 : m3);
            }
        int bestc = 0; float bestn = -1.f;
        #pragma unroll
        for (int j = 0; j < 4; j++) {
            float nn = 0.f;
            #pragma unroll
            for (int i = 0; i < 4; i++) nn = fmaf(adj[i][j], adj[i][j], nn);
            if (nn > bestn) { bestn = nn; bestc = j; }
        }
        float qn = __fdividef(1.f, sqrtf(bestn));
        float q0 = adj[0][bestc] * qn, q1v = adj[1][bestc] * qn;
        float q2v = adj[2][bestc] * qn, q3v = adj[3][bestc] * qn;

        float R[3][3] = {
            {1.f-2.f*(q2v*q2v+q3v*q3v), 2.f*(q1v*q2v-q0*q3v),      2.f*(q1v*q3v+q0*q2v)},
            {2.f*(q1v*q2v+q0*q3v),      1.f-2.f*(q1v*q1v+q3v*q3v), 2.f*(q2v*q3v-q0*q1v)},
            {2.f*(q1v*q3v-q0*q2v),      2.f*(q2v*q3v+q0*q1v),      1.f-2.f*(q1v*q1v+q2v*q2v)}};

        float f1 = 0.f, f2 = 0.f;
        for (int i = 0; i < 3; i++)
            for (int j = 0; j < 3; j++) {
                float Hf = (float)(H[i][j] * scl);
                f1 = fmaf(R[i][j], Hf, f1);
                f2 = fmaf(R[j][i], Hf, f2);
            }
        if (f2 > f1) {
            for (int i = 0; i < 3; i++)
                for (int j = i + 1; j < 3; j++) { float tmp = R[i][j]; R[i][j] = R[j][i]; R[j][i] = tmp; }
        }

        for (int i = 0; i < 3; i++)
            for (int j = 0; j < 3; j++) sR[bb][i*3+j] = R[i][j];
        for (int i = 0; i < 3; i++) {
            sR[bb][9+i]  = (float)(sg[i] * invW);
            sR[bb][12+i] = (float)(sx[i] * invW);
        }
    }
    __syncthreads();

    {
        int bb = tid >> 6;       // 64 threads per batch
        int at = tid & 63;

        float R00 = sR[bb][0], R01 = sR[bb][1], R02 = sR[bb][2];
        float R10 = sR[bb][3], R11 = sR[bb][4], R12 = sR[bb][5];
        float R20 = sR[bb][6], R21 = sR[bb][7], R22 = sR[bb][8];
        float mg0 = sR[bb][9],  mg1 = sR[bb][10], mg2 = sR[bb][11];
        float mx0 = sR[bb][12], mx1 = sR[bb][13], mx2 = sR[bb][14];

        const float* xb = x  + (size_t)bb * NATOM * 3;
        const float* gb = gt + (size_t)bb * NATOM * 3;
        const float* mb = gmask + (size_t)bb * NATOM;

        double s = 0.0;
        for (int k = 0; k < NATOM / 64; k++) {
            int l = k * 64 + at;
            float g0 = gb[3*l+0] - mg0, g1 = gb[3*l+1] - mg1, g2 = gb[3*l+2] - mg2;
            float c0 = R00*g0 + R01*g1 + R02*g2 + mx0;
            float c1 = R10*g0 + R11*g1 + R12*g2 + mx1;
            float c2 = R20*g0 + R21*g1 + R22*g2 + mx2;
            float e0 = xb[3*l+0] - c0, e1 = xb[3*l+1] - c1, e2 = xb[3*l+2] - c2;
            float e = e0*e0 + e1*e1 + e2*e2;
            s += (double)(e * g_watom[bb][l] * mb[l]);
        }

        for (int off = 16; off > 0; off >>= 1) s += __shfl_xor_sync(0xffffffffu, s, off);
        if (lane == 0) sred[warp] = s;
        __syncthreads();

        if (tid == 0) {
            double loss = 0.0;
            for (int bb2 = 0; bb2 < BATCH; bb2++) {
                double A[4];
                for (int q = 0; q < 4; q++) {
                    double v = 0.0;
                    for (int k = 0; k < NBUK; k++) v += g_acc[bb2][q][k];
                    A[q] = v;
                }
                double mse = sred[bb2 * 2] + sred[bb2 * 2 + 1];
                double lbond = A[0] / A[1];
                double llddt = 1.0 - A[2] / A[3];
                double lmse  = (mse / g_mom[bb2][1]) * (1.0 / 3.0);
                double tv = (double)t[bb2];
                double wt = (tv * tv + 256.0) / ((tv + 16.0) * (tv + 16.0));
                loss += wt * (lmse + lbond) + llddt;
            }
            out[0] = (float)(loss / BATCH);

            // reset accumulators for graph replay
            for (int bb2 = 0; bb2 < BATCH; bb2++) {
                for (int q = 0; q < 4; q++)
                    for (int k = 0; k < NBUK; k++) g_acc[bb2][q][k] = 0.0;
                for (int q = 0; q < 17; q++) g_mom[bb2][q] = 0.0;
            }
            __threadfence();
            atomicExch(&g_done, 0u);
        }
    }
}

// ---------------- launch ---------------------------------------------------
extern "C" void kernel_launch(void* const* d_in, const int* in_sizes, int n_in,
                              void* d_out, int out_size) {
    const float* x   = (const float*)d_in[0];
    const float* gt  = (const float*)d_in[1];
    const float* gm  = (const float*)d_in[2];
    const float* isp = (const float*)d_in[3];
    const float* isd = (const float*)d_in[4];
    const float* isr = (const float*)d_in[5];
    const float* isl = (const float*)d_in[6];
    const float* tb  = (const float*)d_in[7];
    const float* tm  = (const float*)d_in[8];
    const int*   npt = (const int*)d_in[9];
    const float* t   = (const float*)d_in[10];
    float* out = (float*)d_out;

    prep_kernel<<<dim3(STILE + ABLK, BATCH), 256>>>(x, gt, gm, isp, isd, isr, isl, tm, npt, tb);
    pair_kernel<<<GRIDB, NTB>>>(x, gt, gm, t, out);
}

// round 14
// speedup vs baseline: 1.0081x; 1.0081x over previous
#include <cuda_runtime.h>
#include <math.h>

#define BATCH 2
#define NTOK 256
#define NATOM 2048
#define TSZ 64                   // atoms per tile
#define NTILE 32                 // NATOM / TSZ
#define TPAIRS 528               // NTILE*(NTILE+1)/2
#define GRIDB (TPAIRS * BATCH)   // 1056 pair blocks
#define NTB 128
#define NBUK 16
#define STILE 64                 // 8x8 grid of 32x32 S tiles per batch
#define ABLK 8                   // atom/moment blocks per batch

// ---------------- device scratch (no allocations allowed) ----------------
__device__ double     g_acc[BATCH][4][NBUK];   // bond_num, bond_den, ce, c (tail resets)
__device__ double     g_mom[BATCH][17];        // tail resets
__device__ ulonglong2 g_posA[BATCH][NATOM];    // (pack(x0,g0), pack(x1,g1))
__device__ ulonglong2 g_posB[BATCH][NATOM];    // (pack(x2,g2), pack(mask,nuc))
__device__ ulonglong2 g_negA[BATCH][NATOM];    // negated coords
__device__ ulonglong2 g_negB[BATCH][NATOM];    // (pack(-x2,-g2), pack(mask,nuc))
__device__ int        g_tok[BATCH][NATOM];
__device__ float      g_watom[BATCH][NATOM];
__device__ float      g_S[BATCH][NTOK * NTOK];
__device__ unsigned   g_done = 0;              // tail resets

__device__ __forceinline__ float sqrt_approx(float v) {
    float y; asm("sqrt.approx.f32 %0, %1;" : "=f"(y) : "f"(v)); return y;
}
__device__ __forceinline__ unsigned long long pack2(float lo, float hi) {
    unsigned long long r; asm("mov.b64 %0, {%1, %2};" : "=l"(r) : "f"(lo), "f"(hi)); return r;
}
__device__ __forceinline__ void unpack2(unsigned long long v, float& lo, float& hi) {
    asm("mov.b64 {%0, %1}, %2;" : "=f"(lo), "=f"(hi) : "l"(v));
}
__device__ __forceinline__ unsigned long long add2(unsigned long long a, unsigned long long b) {
    unsigned long long r; asm("add.rn.f32x2 %0, %1, %2;" : "=l"(r) : "l"(a), "l"(b)); return r;
}
__device__ __forceinline__ unsigned long long fma2(unsigned long long a, unsigned long long b,
                                                   unsigned long long c) {
    unsigned long long r; asm("fma.rn.f32x2 %0, %1, %2, %3;" : "=l"(r) : "l"(a), "l"(b), "l"(c)); return r;
}
__device__ __forceinline__ float det3f(float a00, float a01, float a02,
                                       float a10, float a11, float a12,
                                       float a20, float a21, float a22) {
    return a00*(a11*a22 - a12*a21) - a01*(a10*a22 - a12*a20) + a02*(a10*a21 - a11*a20);
}

// ================= Kernel A: prep (unchanged) ==============================
__global__ void __launch_bounds__(256)
prep_kernel(const float* __restrict__ x, const float* __restrict__ gt,
            const float* __restrict__ gmask,
            const float* __restrict__ isp, const float* __restrict__ isd,
            const float* __restrict__ isr, const float* __restrict__ isl,
            const float* __restrict__ tmask, const int* __restrict__ npt,
            const float* __restrict__ tb) {
    int b   = blockIdx.y;
    int tid = threadIdx.x;
    int lane = tid & 31, warp = tid >> 5;
    const float* tbb = tb + (size_t)b * NTOK * NTOK;

    if (blockIdx.x < STILE) {
        int tI = (blockIdx.x >> 3) << 5;
        int tJ = (blockIdx.x & 7) << 5;

        __shared__ float tA[32][33];
        __shared__ float tB[32][33];
        __shared__ float aI[32], pI[32], aJ[32], pJ[32];

        int r0 = tid >> 5;
        int c  = tid & 31;
        #pragma unroll
        for (int pss = 0; pss < 4; pss++) {
            int r = pss * 8 + r0;
            tA[r][c] = tbb[(tI + r) * NTOK + tJ + c];
            tB[r][c] = tbb[(tJ + r) * NTOK + tI + c];
        }
        if (tid < 32) {
            float tm = tmask[b * NTOK + tI + tid];
            aI[tid] = isl[b * NTOK + tI + tid] * tm;
            pI[tid] = (isp[b*NTOK+tI+tid] + isd[b*NTOK+tI+tid] + isr[b*NTOK+tI+tid]) * tm;
        } else if (tid < 64) {
            int q = tid - 32;
            float tm = tmask[b * NTOK + tJ + q];
            aJ[q] = isl[b * NTOK + tJ + q] * tm;
            pJ[q] = (isp[b*NTOK+tJ+q] + isd[b*NTOK+tJ+q] + isr[b*NTOK+tJ+q]) * tm;
        }
        __syncthreads();

        #pragma unroll
        for (int pss = 0; pss < 4; pss++) {
            int ri = pss * 8 + r0;
            g_S[b][(tI + ri) * NTOK + tJ + c] =
                tA[ri][c] * aI[ri] * pJ[c] + tB[c][ri] * aJ[c] * pI[ri];
        }
        return;
    }

    __shared__ int   cum[NTOK];
    __shared__ float s_nuc[NTOK], s_w[NTOK], s_ab[NTOK];

    {
        float tm = tmask[b * NTOK + tid];
        float dv = isd[b * NTOK + tid];
        float rv = isr[b * NTOK + tid];
        float lv = isl[b * NTOK + tid];
        float pv = isp[b * NTOK + tid];
        s_nuc[tid] = (dv + rv) * tm;
        s_w[tid]   = (1.0f + 5.0f * dv + 5.0f * rv + 10.0f * lv) * tm;
        s_ab[tid]  = (lv * tm) * ((pv + dv + rv) * tm);
        cum[tid]   = npt[b * NTOK + tid];
    }
    __syncthreads();
    for (int off = 1; off < NTOK; off <<= 1) {
        int v = (tid >= off) ? cum[tid - off] : 0;
        __syncthreads();
        cum[tid] += v;
        __syncthreads();
    }
    int total = cum[NTOK - 1];

    const float* xb = x  + (size_t)b * NATOM * 3;
    const float* gb = gt + (size_t)b * NATOM * 3;
    const float* mb = gmask + (size_t)b * NATOM;

    int l = (int)(blockIdx.x - STILE) * 256 + tid;
    int ls = l < total ? l : (total > 0 ? total - 1 : 0);
    int lo = 0, hi = NTOK - 1;
    while (lo < hi) {
        int mid = (lo + hi) >> 1;
        if (cum[mid] > ls) hi = mid; else lo = mid + 1;
    }
    int tok = lo;
    float valid = (l < total) ? 1.f : 0.f;
    float nuc  = s_nuc[tok] * valid;
    float w_at = s_w[tok] * valid;
    float ab   = s_ab[tok] * valid;

    float mk = mb[l];
    float x0 = xb[3*l+0], x1 = xb[3*l+1], x2 = xb[3*l+2];
    float g0 = gb[3*l+0], g1 = gb[3*l+1], g2 = gb[3*l+2];

    g_posA[b][l] = make_ulonglong2(pack2(x0, g0), pack2(x1, g1));
    g_posB[b][l] = make_ulonglong2(pack2(x2, g2), pack2(mk, nuc));
    g_negA[b][l] = make_ulonglong2(pack2(-x0, -g0), pack2(-x1, -g1));
    g_negB[b][l] = make_ulonglong2(pack2(-x2, -g2), pack2(mk, nuc));
    g_tok[b][l]   = tok;
    g_watom[b][l] = w_at;

    float s[18];
    float wm = w_at * mk;
    s[0] = wm; s[1] = mk;
    s[2] = wm*x0; s[3] = wm*x1; s[4] = wm*x2;
    s[5] = wm*g0; s[6] = wm*g1; s[7] = wm*g2;
    s[8]  = wm*x0*g0; s[9]  = wm*x0*g1; s[10] = wm*x0*g2;
    s[11] = wm*x1*g0; s[12] = wm*x1*g1; s[13] = wm*x1*g2;
    s[14] = wm*x2*g0; s[15] = wm*x2*g1; s[16] = wm*x2*g2;
    s[17] = ab * __ldg(&tbb[tok * NTOK + tok]) * mk * mk;

    __shared__ double redm[8][18];
    #pragma unroll
    for (int q = 0; q < 18; q++) {
        double v = (double)s[q];
        for (int off = 16; off > 0; off >>= 1) v += __shfl_xor_sync(0xffffffffu, v, off);
        if (lane == 0) redm[warp][q] = v;
    }
    __syncthreads();
    if (tid < 17) {
        double v = 0.0;
        #pragma unroll
        for (int ww = 0; ww < 8; ww++) v += redm[ww][tid];
        atomicAdd(&g_mom[b][tid], v);
    }
    if (tid == 17) {
        double v = 0.0;
        #pragma unroll
        for (int ww = 0; ww < 8; ww++) v += redm[ww][17];
        atomicAdd(&g_acc[b][1][0], v);
    }
}

// ================= Kernel B: pairwise + tail ==============================
// Thread owns TWO adjacent column atoms (registers); iterates 16 rows (smem).
// Row-side loads/unpacks amortized over 2 pairs; 2 independent FP chains.
__device__ __forceinline__ void pair_body(
    ulonglong2 cA, ulonglong2 cB, float pm,
    ulonglong2 rA, ulonglong2 rB, float rnuc_cnuc, float wS,
    unsigned long long EPS2,
    float& a0, float& a1, float& a2, float& a3)
{
    const float n1 = 0.846045767f,  n2 = 0.187663961f,  n3 = 0.0091748690f;
    const float q1 = 1.128061023f,  q2 = 0.375327923f,  q3 = 0.036699476f, q4 = 0.00055308437f;

    unsigned long long d0 = add2(cA.x, rA.x);
    unsigned long long d1 = add2(cA.y, rA.y);
    unsigned long long d2 = add2(cB.x, rB.x);
    unsigned long long tt = fma2(d0, d0, EPS2);
    tt = fma2(d1, d1, tt);
    tt = fma2(d2, d2, tt);
    float ssx, ssg;
    unpack2(tt, ssx, ssg);
    float dxv = sqrt_approx(ssx);
    float dgv = sqrt_approx(ssg);

    float diff = dxv - dgv;
    float wbs = wS * pm;
    a0 = fmaf(diff * diff, wbs, a0);
    a1 += wbs;

    float d = fminf(fabsf(diff), 20.f);
    float E = __expf(d);
    float num = fmaf(fmaf(fmaf(n3, E, n2), E, n1), E, 1.f);
    float den = fmaf(fmaf(fmaf(fmaf(q4, E, q3), E, q2), E, q1), E, 1.f);
    float e   = __fdividef(num, den);

    float cc = (dgv < 15.f) ? 2.f : ((dgv < 30.f) ? rnuc_cnuc : 0.f);
    float csum = cc * pm;

    a2 = fmaf(csum, e, a2);
    a3 += csum;
}

template<bool DIAG>
__device__ __forceinline__ void pair_loop2(
    int rq, int c0,
    ulonglong2 cA0, ulonglong2 cB0, float cm0, float cn0, const float* Scol0,
    ulonglong2 cA1, ulonglong2 cB1, float cm1, float cn1, const float* Scol1,
    const ulonglong2* srA, const ulonglong2* srB, const int* srT,
    float& a0, float& a1, float& a2, float& a3)
{
    int i0 = rq << 4;
    const unsigned long long EPS2 = pack2(1e-12f, 1e-12f);

    #pragma unroll 4
    for (int k = 0; k < 16; k++) {
        int i = i0 + k;
        ulonglong2 rA = srA[i], rB = srB[i];
        float rmask, rnuc;
        unpack2(rB.y, rmask, rnuc);
        int off = srT[i] * NTOK;
        float wS0 = __ldg(Scol0 + off);
        float wS1 = __ldg(Scol1 + off);

        float pm0 = cm0 * rmask;
        float pm1 = cm1 * rmask;
        if (DIAG) {
            pm0 = (c0     > i) ? pm0 : 0.f;
            pm1 = (c0 + 1 > i) ? pm1 : 0.f;
        }

        pair_body(cA0, cB0, pm0, rA, rB, rnuc + cn0, wS0, EPS2, a0, a1, a2, a3);
        pair_body(cA1, cB1, pm1, rA, rB, rnuc + cn1, wS1, EPS2, a0, a1, a2, a3);
    }
}

__global__ void __launch_bounds__(NTB, 8)
pair_kernel(const float* __restrict__ x, const float* __restrict__ gt,
            const float* __restrict__ gmask, const float* __restrict__ t,
            float* __restrict__ out) {
    int blk = blockIdx.x;
    int tid = threadIdx.x;
    int b = blk & 1;
    int p = blk >> 1;
    int I = 0, rem = p;
    while (rem >= (NTILE - I)) { rem -= (NTILE - I); I++; }
    int J = I + rem;

    __shared__ ulonglong2 srA[TSZ], srB[TSZ];
    __shared__ int        srT[TSZ];

    // row tile I (negated) into smem
    if (tid < TSZ) {
        srA[tid]  = g_negA[b][I * TSZ + tid];
        srT[tid]  = g_tok[b][I * TSZ + tid];
    } else {
        int li = tid - TSZ;
        srB[li] = g_negB[b][I * TSZ + li];
    }

    // two column atoms per thread (positive copies), from global
    int cp = tid & 31;          // column pair index
    int rq = tid >> 5;          // row quarter (0-3)
    int c0 = cp << 1;
    int lc = J * TSZ + c0;
    ulonglong2 cA0 = g_posA[b][lc],     cB0 = g_posB[b][lc];
    ulonglong2 cA1 = g_posA[b][lc + 1], cB1 = g_posB[b][lc + 1];
    float cm0, cn0, cm1, cn1;
    unpack2(cB0.y, cm0, cn0);
    unpack2(cB1.y, cm1, cn1);
    const float* Scol0 = &g_S[b][g_tok[b][lc]];
    const float* Scol1 = &g_S[b][g_tok[b][lc + 1]];
    __syncthreads();

    float a0 = 0.f, a1 = 0.f, a2 = 0.f, a3 = 0.f;
    if (I == J) pair_loop2<true >(rq, c0, cA0, cB0, cm0, cn0, Scol0,
                                  cA1, cB1, cm1, cn1, Scol1,
                                  srA, srB, srT, a0, a1, a2, a3);
    else        pair_loop2<false>(rq, c0, cA0, cB0, cm0, cn0, Scol0,
                                  cA1, cB1, cm1, cn1, Scol1,
                                  srA, srB, srT, a0, a1, a2, a3);

    int lane = tid & 31, warp = tid >> 5;
    {
        __shared__ float red2[4][4];
        float vals[4] = {a0, a1, a2, a3};
        #pragma unroll
        for (int k = 0; k < 4; k++) {
            float v = vals[k];
            for (int off = 16; off > 0; off >>= 1) v += __shfl_xor_sync(0xffffffffu, v, off);
            if (lane == 0) red2[warp][k] = v;
        }
        __syncthreads();
        if (tid < 4) {
            float ssum = red2[0][tid] + red2[1][tid] + red2[2][tid] + red2[3][tid];
            atomicAdd(&g_acc[b][tid][(blk >> 1) & (NBUK - 1)], (double)ssum);
        }
    }

    // ---- done counter: last finishing block runs the tail -----------------
    __shared__ int s_last;
    __threadfence();
    __syncthreads();
    if (tid == 0) {
        unsigned v = atomicAdd(&g_done, 1u);
        s_last = (v == GRIDB - 1) ? 1 : 0;
    }
    __syncthreads();
    if (!s_last) return;
    __threadfence();   // acquire

    // =========== tail: QCP Kabsch + weighted MSE + final ====================
    __shared__ float sR[BATCH][15];
    __shared__ double sred[4];

    if (tid < BATCH) {
        int bb = tid;
        double W = g_mom[bb][0];
        double invW = 1.0 / W;
        double sx[3] = {g_mom[bb][2], g_mom[bb][3], g_mom[bb][4]};
        double sg[3] = {g_mom[bb][5], g_mom[bb][6], g_mom[bb][7]};
        double H[3][3];
        for (int i = 0; i < 3; i++)
            for (int j = 0; j < 3; j++)
                H[i][j] = g_mom[bb][8 + i * 3 + j] - sx[i] * sg[j] * invW;

        double Sxx = H[0][0], Sxy = H[1][0], Sxz = H[2][0];
        double Syx = H[0][1], Syy = H[1][1], Syz = H[2][1];
        double Szx = H[0][2], Szy = H[1][2], Szz = H[2][2];

        double Nd[4][4] = {
            { Sxx+Syy+Szz,  Syz-Szy,       Szx-Sxz,       Sxy-Syx      },
            { Syz-Szy,      Sxx-Syy-Szz,   Sxy+Syx,       Szx+Sxz      },
            { Szx-Sxz,      Sxy+Syx,      -Sxx+Syy-Szz,   Syz+Szy      },
            { Sxy-Syx,      Szx+Sxz,       Syz+Szy,      -Sxx-Syy+Szz  }};

        double fro = 0.0;
        for (int i = 0; i < 4; i++) for (int j = 0; j < 4; j++) fro += Nd[i][j]*Nd[i][j];
        double scl = 1.0 / sqrt(fro + 1e-300);

        float N[4][4];
        for (int i = 0; i < 4; i++)
            for (int j = 0; j < 4; j++) N[i][j] = (float)(Nd[i][j] * scl);

        float N2[4][4]; float t3 = 0.f, t4 = 0.f;
        #pragma unroll
        for (int i = 0; i < 4; i++)
            #pragma unroll
            for (int j = 0; j < 4; j++) {
                float v = 0.f;
                #pragma unroll
                for (int k = 0; k < 4; k++) v = fmaf(N[i][k], N[k][j], v);
                N2[i][j] = v;
            }
        #pragma unroll
        for (int i = 0; i < 4; i++)
            #pragma unroll
            for (int j = 0; j < 4; j++) {
                t3 = fmaf(N2[i][j], N[i][j], t3);
                t4 = fmaf(N2[i][j], N2[i][j], t4);
            }
        const float a2c = -0.5f;
        float a1c = -t3 * (1.f / 3.f);
        float a0c = 0.125f - 0.25f * t4;

        float lam = 1.0f;
        #pragma unroll
        for (int it = 0; it < 16; it++) {
            float pp = fmaf(fmaf(fmaf(lam, lam, a2c), lam, a1c), lam, a0c);
            float dp = fmaf(fmaf(4.f, lam * lam, 2.f * a2c), lam, a1c);
            lam -= __fdividef(pp, dp);
        }

        float M[4][4];
        for (int i = 0; i < 4; i++)
            for (int j = 0; j < 4; j++) M[i][j] = N[i][j] - ((i == j) ? lam : 0.f);

        float adj[4][4];
        const int rows[4][3] = {{1,2,3},{0,2,3},{0,1,3},{0,1,2}};
        #pragma unroll
        for (int i = 0; i < 4; i++)
            #pragma unroll
            for (int j = 0; j < 4; j++) {
                const int* rr = rows[j];
                const int* cc = rows[i];
                float m3 = det3f(M[rr[0]][cc[0]], M[rr[0]][cc[1]], M[rr[0]][cc[2]],
                                 M[rr[1]][cc[0]], M[rr[1]][cc[1]], M[rr[1]][cc[2]],
                                 M[rr[2]][cc[0]], M[rr[2]][cc[1]], M[rr[2]][cc[2]]);
                adj[i][j] = (((i + j) & 1) ? -m3 : m3);
            }
        int bestc = 0; float bestn = -1.f;
        #pragma unroll
        for (int j = 0; j < 4; j++) {
            float nn = 0.f;
            #pragma unroll
            for (int i = 0; i < 4; i++) nn = fmaf(adj[i][j], adj[i][j], nn);
            if (nn > bestn) { bestn = nn; bestc = j; }
        }
        float qn = __fdividef(1.f, sqrtf(bestn));
        float q0 = adj[0][bestc] * qn, q1v = adj[1][bestc] * qn;
        float q2v = adj[2][bestc] * qn, q3v = adj[3][bestc] * qn;

        float R[3][3] = {
            {1.f-2.f*(q2v*q2v+q3v*q3v), 2.f*(q1v*q2v-q0*q3v),      2.f*(q1v*q3v+q0*q2v)},
            {2.f*(q1v*q2v+q0*q3v),      1.f-2.f*(q1v*q1v+q3v*q3v), 2.f*(q2v*q3v-q0*q1v)},
            {2.f*(q1v*q3v-q0*q2v),      2.f*(q2v*q3v+q0*q1v),      1.f-2.f*(q1v*q1v+q2v*q2v)}};

        float f1 = 0.f, f2 = 0.f;
        for (int i = 0; i < 3; i++)
            for (int j = 0; j < 3; j++) {
                float Hf = (float)(H[i][j] * scl);
                f1 = fmaf(R[i][j], Hf, f1);
                f2 = fmaf(R[j][i], Hf, f2);
            }
        if (f2 > f1) {
            for (int i = 0; i < 3; i++)
                for (int j = i + 1; j < 3; j++) { float tmp = R[i][j]; R[i][j] = R[j][i]; R[j][i] = tmp; }
        }

        for (int i = 0; i < 3; i++)
            for (int j = 0; j < 3; j++) sR[bb][i*3+j] = R[i][j];
        for (int i = 0; i < 3; i++) {
            sR[bb][9+i]  = (float)(sg[i] * invW);
            sR[bb][12+i] = (float)(sx[i] * invW);
        }
    }
    __syncthreads();

    {
        int bb = tid >> 6;       // 64 threads per batch
        int at = tid & 63;

        float R00 = sR[bb][0], R01 = sR[bb][1], R02 = sR[bb][2];
        float R10 = sR[bb][3], R11 = sR[bb][4], R12 = sR[bb][5];
        float R20 = sR[bb][6], R21 = sR[bb][7], R22 = sR[bb][8];
        float mg0 = sR[bb][9],  mg1 = sR[bb][10], mg2 = sR[bb][11];
        float mx0 = sR[bb][12], mx1 = sR[bb][13], mx2 = sR[bb][14];

        const float* xb = x  + (size_t)bb * NATOM * 3;
        const float* gb = gt + (size_t)bb * NATOM * 3;
        const float* mb = gmask + (size_t)bb * NATOM;

        double s = 0.0;
        for (int k = 0; k < NATOM / 64; k++) {
            int l = k * 64 + at;
            float g0 = gb[3*l+0] - mg0, g1 = gb[3*l+1] - mg1, g2 = gb[3*l+2] - mg2;
            float c0 = R00*g0 + R01*g1 + R02*g2 + mx0;
            float c1 = R10*g0 + R11*g1 + R12*g2 + mx1;
            float c2 = R20*g0 + R21*g1 + R22*g2 + mx2;
            float e0 = xb[3*l+0] - c0, e1 = xb[3*l+1] - c1, e2 = xb[3*l+2] - c2;
            float e = e0*e0 + e1*e1 + e2*e2;
            s += (double)(e * g_watom[bb][l] * mb[l]);
        }

        for (int off = 16; off > 0; off >>= 1) s += __shfl_xor_sync(0xffffffffu, s, off);
        if (lane == 0) sred[warp] = s;
        __syncthreads();

        if (tid == 0) {
            double loss = 0.0;
            for (int bb2 = 0; bb2 < BATCH; bb2++) {
                double A[4];
                for (int q = 0; q < 4; q++) {
                    double v = 0.0;
                    for (int k = 0; k < NBUK; k++) v += g_acc[bb2][q][k];
                    A[q] = v;
                }
                double mse = sred[bb2 * 2] + sred[bb2 * 2 + 1];
                double lbond = A[0] / A[1];
                double llddt = 1.0 - A[2] / A[3];
                double lmse  = (mse / g_mom[bb2][1]) * (1.0 / 3.0);
                double tv = (double)t[bb2];
                double wt = (tv * tv + 256.0) / ((tv + 16.0) * (tv + 16.0));
                loss += wt * (lmse + lbond) + llddt;
            }
            out[0] = (float)(loss / BATCH);

            // reset accumulators for graph replay
            for (int bb2 = 0; bb2 < BATCH; bb2++) {
                for (int q = 0; q < 4; q++)
                    for (int k = 0; k < NBUK; k++) g_acc[bb2][q][k] = 0.0;
                for (int q = 0; q < 17; q++) g_mom[bb2][q] = 0.0;
            }
            __threadfence();
            atomicExch(&g_done, 0u);
        }
    }
}

// ---------------- launch ---------------------------------------------------
extern "C" void kernel_launch(void* const* d_in, const int* in_sizes, int n_in,
                              void* d_out, int out_size) {
    const float* x   = (const float*)d_in[0];
    const float* gt  = (const float*)d_in[1];
    const float* gm  = (const float*)d_in[2];
    const float* isp = (const float*)d_in[3];
    const float* isd = (const float*)d_in[4];
    const float* isr = (const float*)d_in[5];
    const float* isl = (const float*)d_in[6];
    const float* tb  = (const float*)d_in[7];
    const float* tm  = (const float*)d_in[8];
    const int*   npt = (const int*)d_in[9];
    const float* t   = (const float*)d_in[10];
    float* out = (float*)d_out;

    prep_kernel<<<dim3(STILE + ABLK, BATCH), 256>>>(x, gt, gm, isp, isd, isr, isl, tm, npt, tb);
    pair_kernel<<<GRIDB, NTB>>>(x, gt, gm, t, out);
}